// round 7
// baseline (speedup 1.0000x reference)
#include <cuda_runtime.h>
#include <cstdint>

#define N_NODES 100000
#define D 128
#define N_EDGES 1600000
#define TILE 32
#define NTILES (N_NODES / TILE)                  // 3125 exact
#define NB_SCAN ((N_NODES + 255) / 256)          // 391

__device__ int g_cnt[N_NODES];
__device__ int g_rs[N_NODES + 1];
__device__ int g_esrc[N_EDGES];
__device__ int g_bsum[512];
__device__ int g_is64;

// ---------------- packed f32x2 helpers (validated) ----------------
__device__ __forceinline__ unsigned long long fma2(unsigned long long a,
                                                   unsigned long long b,
                                                   unsigned long long c) {
    unsigned long long d;
    asm("fma.rn.f32x2 %0, %1, %2, %3;" : "=l"(d) : "l"(a), "l"(b), "l"(c));
    return d;
}
__device__ __forceinline__ unsigned long long dup2(float a) {
    unsigned long long d;
    asm("mov.b64 %0, {%1, %1};" : "=l"(d) : "f"(a));
    return d;
}
__device__ __forceinline__ float2 unpack2(unsigned long long v) {
    float2 r;
    asm("mov.b64 {%0, %1}, %2;" : "=f"(r.x), "=f"(r.y) : "l"(v));
    return r;
}

__device__ __forceinline__ void load_edge(const void* src_raw, const void* dst_raw,
                                          int e, int is64, int& s, int& d) {
    if (is64) {
        s = (int)((const long long*)src_raw)[e];
        d = (int)((const long long*)dst_raw)[e];
    } else {
        s = ((const int*)src_raw)[e];
        d = ((const int*)dst_raw)[e];
    }
}

// ---------------- kernel 1: zero counts + dtype sniff ----------------
__global__ void zero_sniff_kernel(const void* __restrict__ src) {
    int i = blockIdx.x * blockDim.x + threadIdx.x;
    if (i < N_NODES) g_cnt[i] = 0;
    if (i == 0) {
        const long long* p = (const long long*)src;
        int ok = 1;
        #pragma unroll 1
        for (int q = 0; q < 64; q++) {
            long long v = p[q];
            if (v < 0 || v >= N_NODES) { ok = 0; break; }
        }
        g_is64 = ok;
    }
}

// ---------------- CSR build (validated) ----------------
__global__ void count_kernel(const void* __restrict__ src_raw,
                             const void* __restrict__ dst_raw) {
    const int is64 = g_is64;
    int idx = blockIdx.x * blockDim.x + threadIdx.x;
    int stride = gridDim.x * blockDim.x;
    for (int e = idx; e < N_EDGES; e += stride) {
        int s, d;
        load_edge(src_raw, dst_raw, e, is64, s, d);
        if ((unsigned)s < N_NODES && (unsigned)d < N_NODES)
            atomicAdd(&g_cnt[d], 1);
    }
}

__global__ void scan1_kernel() {
    __shared__ int sm[256];
    int gi = blockIdx.x * 256 + threadIdx.x;
    sm[threadIdx.x] = (gi < N_NODES) ? g_cnt[gi] : 0;
    __syncthreads();
    for (int off = 128; off > 0; off >>= 1) {
        if (threadIdx.x < off) sm[threadIdx.x] += sm[threadIdx.x + off];
        __syncthreads();
    }
    if (threadIdx.x == 0) g_bsum[blockIdx.x] = sm[0];
}
__global__ void scan2_kernel() {
    __shared__ int sm[512];
    int t = threadIdx.x;
    sm[t] = (t < NB_SCAN) ? g_bsum[t] : 0;
    __syncthreads();
    for (int off = 1; off < 512; off <<= 1) {
        int v = (t >= off) ? sm[t - off] : 0;
        __syncthreads();
        sm[t] += v;
        __syncthreads();
    }
    int ex = (t == 0) ? 0 : sm[t - 1];
    if (t < NB_SCAN) g_bsum[t] = ex;
    if (t == NB_SCAN) g_rs[N_NODES] = sm[NB_SCAN - 1];
}
__global__ void scan3_kernel() {
    __shared__ int sm[256];
    int b = blockIdx.x, t = threadIdx.x;
    int gi = b * 256 + t;
    int c = (gi < N_NODES) ? g_cnt[gi] : 0;
    sm[t] = c;
    __syncthreads();
    for (int off = 1; off < 256; off <<= 1) {
        int v = (t >= off) ? sm[t - off] : 0;
        __syncthreads();
        sm[t] += v;
        __syncthreads();
    }
    int ex = sm[t] - c;
    if (gi < N_NODES) {
        g_rs[gi] = g_bsum[b] + ex;
        g_cnt[gi] = 0;
    }
}

__global__ void fill_kernel(const void* __restrict__ src_raw,
                            const void* __restrict__ dst_raw) {
    const int is64 = g_is64;
    int idx = blockIdx.x * blockDim.x + threadIdx.x;
    int stride = gridDim.x * blockDim.x;
    for (int e = idx; e < N_EDGES; e += stride) {
        int s, d;
        load_edge(src_raw, dst_raw, e, is64, s, d);
        if ((unsigned)s < N_NODES && (unsigned)d < N_NODES) {
            int pos = atomicAdd(&g_cnt[d], 1);
            g_esrc[g_rs[d] + pos] = s;
        }
    }
}

// ---------------- fused kernel: warp-specialized ping-pong ----------------
// 384 threads: warps 0-3 compute, warps 4-11 gather. Two-pass GEMM
// (self then neigh) to halve live A registers and avoid spills.
__global__ __launch_bounds__(384, 1)
void fused_kernel(const float* __restrict__ h,
                  const float* __restrict__ Ws,
                  const float* __restrict__ Wn,
                  float* __restrict__ out) {
    extern __shared__ float sm[];
    float* sWs = sm;
    float* sWn = sm + 16384;
    float* sX  = sm + 32768;  // [2 bufs][self 4096 | neigh 4096]

    int tid = threadIdx.x, wid = tid >> 5, lane = tid & 31;
    const bool is_gather = (wid >= 4);

    auto fill_tile = [&](int tile, int buf) {
        float* bXs = sX + buf * 8192;
        float* bXn = bXs + 4096;
        int gwid = wid - 4;  // 0..7
        #pragma unroll 1
        for (int rr = 0; rr < 4; rr++) {
            int r = gwid * 4 + rr;
            int row = tile * TILE + r;
            float4 self = reinterpret_cast<const float4*>(h + (size_t)row * D)[lane];
            int beg = g_rs[row], end = g_rs[row + 1];
            float inv = 1.0f / fmaxf((float)(end - beg), 1.0f);
            float4 acc = make_float4(0.f, 0.f, 0.f, 0.f);
            int e = beg;
            #pragma unroll 1
            for (; e + 8 <= end; e += 8) {
                int si[8];
                #pragma unroll
                for (int q = 0; q < 8; q++) si[q] = g_esrc[e + q];
                float4 v[8];
                #pragma unroll
                for (int q = 0; q < 8; q++)
                    v[q] = reinterpret_cast<const float4*>(h + (size_t)si[q] * D)[lane];
                #pragma unroll
                for (int q = 0; q < 8; q++) {
                    acc.x += v[q].x; acc.y += v[q].y;
                    acc.z += v[q].z; acc.w += v[q].w;
                }
            }
            #pragma unroll 1
            for (; e < end; e++) {
                int s0 = g_esrc[e];
                float4 v0 = reinterpret_cast<const float4*>(h + (size_t)s0 * D)[lane];
                acc.x += v0.x; acc.y += v0.y; acc.z += v0.z; acc.w += v0.w;
            }
            reinterpret_cast<float4*>(bXs + r * D)[lane] = self;
            reinterpret_cast<float4*>(bXn + r * D)[lane] =
                make_float4(acc.x * inv, acc.y * inv, acc.z * inv, acc.w * inv);
        }
    };

    // prologue
    int t = blockIdx.x;
    if (is_gather) {
        if (t < NTILES) fill_tile(t, 0);
    } else {
        for (int i = tid; i < 4096; i += 128) {
            reinterpret_cast<float4*>(sWs)[i] = reinterpret_cast<const float4*>(Ws)[i];
            reinterpret_cast<float4*>(sWn)[i] = reinterpret_cast<const float4*>(Wn)[i];
        }
    }
    __syncthreads();

    int p = 0;
    int c0 = lane * 4;
    int r0 = wid * 8;

    for (; t < NTILES; t += gridDim.x) {
        if (is_gather) {
            int tn = t + gridDim.x;
            if (tn < NTILES) fill_tile(tn, p ^ 1);
        } else {
            float* bXs = sX + p * 8192;
            float* bXn = bXs + 4096;

            unsigned long long accu[8][2];
            #pragma unroll
            for (int i = 0; i < 8; i++) { accu[i][0] = 0ull; accu[i][1] = 0ull; }

            // ---- pass 1: self x Ws ----
            #pragma unroll 1
            for (int kk = 0; kk < D; kk += 4) {
                float4 a[8];
                #pragma unroll
                for (int i = 0; i < 8; i++)
                    a[i] = *reinterpret_cast<const float4*>(bXs + (r0 + i) * D + kk);
                #pragma unroll
                for (int dk = 0; dk < 4; dk++) {
                    ulonglong2 w2 = *reinterpret_cast<const ulonglong2*>(sWs + (kk + dk) * D + c0);
                    #pragma unroll
                    for (int i = 0; i < 8; i++) {
                        unsigned long long a2 = dup2(reinterpret_cast<const float*>(&a[i])[dk]);
                        accu[i][0] = fma2(a2, w2.x, accu[i][0]);
                        accu[i][1] = fma2(a2, w2.y, accu[i][1]);
                    }
                }
            }
            // ---- pass 2: neigh x Wn ----
            #pragma unroll 1
            for (int kk = 0; kk < D; kk += 4) {
                float4 a[8];
                #pragma unroll
                for (int i = 0; i < 8; i++)
                    a[i] = *reinterpret_cast<const float4*>(bXn + (r0 + i) * D + kk);
                #pragma unroll
                for (int dk = 0; dk < 4; dk++) {
                    ulonglong2 w2 = *reinterpret_cast<const ulonglong2*>(sWn + (kk + dk) * D + c0);
                    #pragma unroll
                    for (int i = 0; i < 8; i++) {
                        unsigned long long a2 = dup2(reinterpret_cast<const float*>(&a[i])[dk]);
                        accu[i][0] = fma2(a2, w2.x, accu[i][0]);
                        accu[i][1] = fma2(a2, w2.y, accu[i][1]);
                    }
                }
            }

            #pragma unroll
            for (int i = 0; i < 8; i++) {
                int row = t * TILE + r0 + i;
                float2 lo = unpack2(accu[i][0]);
                float2 hi = unpack2(accu[i][1]);
                *reinterpret_cast<float4*>(out + (size_t)row * D + c0) =
                    make_float4(lo.x, lo.y, hi.x, hi.y);
            }
        }
        __syncthreads();
        p ^= 1;
    }
}

// ---------------- launch ----------------
extern "C" void kernel_launch(void* const* d_in, const int* in_sizes, int n_in,
                              void* d_out, int out_size) {
    const float* h      = (const float*)d_in[0];
    const void*  src    = d_in[1];
    const void*  dst    = d_in[2];
    const float* Wself  = (const float*)d_in[3];
    const float* Wneigh = (const float*)d_in[4];
    float*       out    = (float*)d_out;

    static bool attr_set = false;
    if (!attr_set) {
        cudaFuncSetAttribute(fused_kernel,
                             cudaFuncAttributeMaxDynamicSharedMemorySize,
                             196608);
        attr_set = true;
    }

    zero_sniff_kernel<<<NB_SCAN, 256>>>(src);
    count_kernel<<<2048, 256>>>(src, dst);
    scan1_kernel<<<NB_SCAN, 256>>>();
    scan2_kernel<<<1, 512>>>();
    scan3_kernel<<<NB_SCAN, 256>>>();
    fill_kernel<<<2048, 256>>>(src, dst);
    fused_kernel<<<152, 384, 196608>>>(h, Wself, Wneigh, out);
}